// round 3
// baseline (speedup 1.0000x reference)
#include <cuda_runtime.h>
#include <cstdint>

// Problem constants
#define T_STEPS 1024
#define B_TOT   256
#define I_DIM   64
#define H_DIM   256
#define O_DIM   16
#define K_TOT   320      // H_DIM + I_DIM (concatenated [h | x])
#define K_PAD   336      // padded row stride for bank-conflict-free LDS (336/4=84, 84 mod 32 = 20, gcd(20,32)=4 -> 8 rows distinct)
#define NB_CTA  8        // batches per CTA
#define N_CTA   32       // 32 * 8 = 256 batches

// Scratch (device globals: no allocation allowed)
__device__ int8_t g_Wcat[H_DIM * K_TOT];          // [h_out][k]  int4 values in int8 (-8..7)
__device__ int8_t g_wo[O_DIM * H_DIM];            // [o][k]      int4 values in int8
__device__ float  g_b128[H_DIM];                  // 128 * b[n]
__device__ int8_t g_xT[(size_t)T_STEPS * B_TOT * I_DIM];  // transposed quantized inputs [t][b][i]

// ---------------------------------------------------------------------------
// Prep kernel 1: quantize weights & bias
// quantize(w, 4) -> clip(rint(w*8), -8, 7)  (value stored as the integer)
// ---------------------------------------------------------------------------
__global__ void prep_weights(const float* __restrict__ Wi,
                             const float* __restrict__ Wr,
                             const float* __restrict__ Wo,
                             const float* __restrict__ b) {
    int i = blockIdx.x * blockDim.x + threadIdx.x;
    const int NW = H_DIM * K_TOT;           // 81920
    const int NO = O_DIM * H_DIM;           // 4096
    if (i < NW) {
        int n = i / K_TOT, k = i % K_TOT;
        float v = (k < H_DIM) ? Wr[n * H_DIM + k] : Wi[n * I_DIM + (k - H_DIM)];
        int q = __float2int_rn(v * 8.0f);
        q = max(-8, min(7, q));
        g_Wcat[i] = (int8_t)q;
    } else if (i < NW + NO) {
        int j = i - NW;
        int q = __float2int_rn(Wo[j] * 8.0f);
        q = max(-8, min(7, q));
        g_wo[j] = (int8_t)q;
    } else if (i < NW + NO + H_DIM) {
        int n = i - (NW + NO);
        g_b128[n] = 128.0f * b[n];
    }
}

// ---------------------------------------------------------------------------
// Prep kernel 2: quantize inputs (8-bit) and transpose [B,T,I] -> [T,B,I]
// quantize(x, 8) -> clip(rint(x*128), -128, 127)
// ---------------------------------------------------------------------------
__global__ void prep_inputs(const float* __restrict__ inp) {
    int t = blockIdx.x;
    int tid = threadIdx.x;
    int i = tid & 63;
    int bq = tid >> 6;          // 0..3
    for (int it = 0; it < 64; it++) {
        int bb = it * 4 + bq;   // 0..255
        float v = inp[(size_t)bb * (T_STEPS * I_DIM) + (size_t)t * I_DIM + i];
        int q = __float2int_rn(v * 128.0f);
        q = max(-128, min(127, q));
        g_xT[(size_t)t * (B_TOT * I_DIM) + bb * I_DIM + i] = (int8_t)q;
    }
}

// ---------------------------------------------------------------------------
// int8 mma.sync helper: D(s32 16x8) += A(s8 16x32, row) * B(s8 32x8, col)
// ---------------------------------------------------------------------------
__device__ __forceinline__ void mma_s8(int* c, const unsigned* a, unsigned b0, unsigned b1) {
    asm volatile(
        "mma.sync.aligned.m16n8k32.row.col.s32.s8.s8.s32 "
        "{%0,%1,%2,%3}, {%4,%5,%6,%7}, {%8,%9}, {%0,%1,%2,%3};"
        : "+r"(c[0]), "+r"(c[1]), "+r"(c[2]), "+r"(c[3])
        : "r"(a[0]), "r"(a[1]), "r"(a[2]), "r"(a[3]), "r"(b0), "r"(b1));
}

// ---------------------------------------------------------------------------
// Recurrent kernel: 32 CTAs x 8 batches, 8 warps, weights register-resident.
// Per step: z^T[h_out][batch] = Wcat @ [h|x]^T ; h_new = q8(modrelu(z)).
// Exact integer arithmetic: z = zi/1024; m*128 = relu(|zi|/8 + 128*b).
// ---------------------------------------------------------------------------
__global__ __launch_bounds__(256, 1) void rnn_kernel(float* __restrict__ out) {
    __shared__ __align__(16) int8_t Abuf[NB_CTA * K_PAD];  // [batch][k] (h: 0..255, x: 256..319)

    const int tid  = threadIdx.x;
    const int w    = tid >> 5;
    const int lane = tid & 31;
    const int g    = lane >> 2;   // groupID (0..7)
    const int tig  = lane & 3;    // thread-in-group
    const int cta  = blockIdx.x;

    // --- Load weight A-fragments into registers (once) ---
    // warp w owns h_out rows [w*32, w*32+32): 2 m16 tiles, 10 k-chunks of 32
    unsigned a[2][10][4];
#pragma unroll
    for (int mt = 0; mt < 2; mt++) {
        const int r0 = w * 32 + mt * 16 + g;
#pragma unroll
        for (int kc = 0; kc < 10; kc++) {
            const int8_t* p = g_Wcat + r0 * K_TOT + kc * 32 + tig * 4;
            a[mt][kc][0] = *(const unsigned*)(p);                    // (g,   k_lo)
            a[mt][kc][1] = *(const unsigned*)(p + 8 * K_TOT);        // (g+8, k_lo)
            a[mt][kc][2] = *(const unsigned*)(p + 16);               // (g,   k_hi)
            a[mt][kc][3] = *(const unsigned*)(p + 8 * K_TOT + 16);   // (g+8, k_hi)
        }
    }
    float bias[4];
#pragma unroll
    for (int mt = 0; mt < 2; mt++) {
        bias[mt * 2 + 0] = g_b128[w * 32 + mt * 16 + g];
        bias[mt * 2 + 1] = g_b128[w * 32 + mt * 16 + g + 8];
    }

    // --- zero A buffer (h0 = 0, pad = 0) ---
    for (int i = tid; i < NB_CTA * K_PAD / 4; i += 256) ((unsigned*)Abuf)[i] = 0;
    __syncthreads();

    // --- preload x_0 into smem (threads 0..127: 512 bytes) ---
    if (tid < 128) {
        unsigned x0 = *(const unsigned*)(g_xT + (size_t)cta * (NB_CTA * I_DIM) + tid * 4);
        *(unsigned*)(Abuf + (tid >> 4) * K_PAD + H_DIM + (tid & 15) * 4) = x0;
    }
    __syncthreads();

    const size_t x_step = (size_t)B_TOT * I_DIM;
    const int8_t* xbase = g_xT + (size_t)cta * (NB_CTA * I_DIM);

    for (int t = 0; t < T_STEPS; t++) {
        // prefetch next step's x slice into a register (latency hidden by mma)
        unsigned xnext = 0;
        if (tid < 128 && t + 1 < T_STEPS)
            xnext = *(const unsigned*)(xbase + (size_t)(t + 1) * x_step + tid * 4);

        int acc0[4] = {0, 0, 0, 0};
        int acc1[4] = {0, 0, 0, 0};
#pragma unroll
        for (int kc = 0; kc < 10; kc++) {
            const int8_t* bp = Abuf + g * K_PAD + kc * 32 + tig * 4;
            unsigned b0 = *(const unsigned*)(bp);
            unsigned b1 = *(const unsigned*)(bp + 16);
            mma_s8(acc0, a[0][kc], b0, b1);
            mma_s8(acc1, a[1][kc], b0, b1);
        }
        __syncthreads();  // all warps done reading step-t operands

        // Epilogue: h_new = clip(rint(sign(z) * relu(|z|+b) * 128), -128, 127)
        //   z = zi/1024  ->  target = sign(zi) * relu(|zi|/8 + 128*b), rni, clamp
#pragma unroll
        for (int mt = 0; mt < 2; mt++) {
            const int* acc = (mt == 0) ? acc0 : acc1;
#pragma unroll
            for (int j = 0; j < 4; j++) {
                int   zi   = acc[j];
                float B128 = bias[mt * 2 + (j >> 1)];
                float fz   = (float)zi;                       // exact (|zi| < 2^20)
                float tt   = fmaf(fabsf(fz), 0.125f, B128);   // |zi|/8 + 128b (single RN, matches ref)
                tt = fmaxf(tt, 0.0f);                         // relu
                float v = copysignf(tt, fz);                  // sign(z)*m*128
                int r = __float2int_rn(v);                    // round half-even
                if (zi == 0) r = 0;                           // jnp.sign(0) == 0
                r = max(-128, min(127, r));
                int row = w * 32 + mt * 16 + g + ((j >> 1) * 8);  // h_out index
                int col = 2 * tig + (j & 1);                      // batch index
                Abuf[col * K_PAD + row] = (int8_t)r;
            }
        }
        if (tid < 128)
            *(unsigned*)(Abuf + (tid >> 4) * K_PAD + H_DIM + (tid & 15) * 4) = xnext;
        __syncthreads();  // h_{t+1}, x_{t+1} visible
    }

    // --- Output head: out[b][o] = (h_last . wo_q) / 1024  (exact in fp32) ---
    if (tid < 128) {
        int b = tid >> 4;   // 0..7
        int o = tid & 15;   // 0..15
        int acc = 0;
        const int8_t* wo = g_wo + o * H_DIM;
        const int8_t* hr = Abuf + b * K_PAD;
#pragma unroll
        for (int k4 = 0; k4 < H_DIM / 4; k4++) {
            int hv = *(const int*)(hr + k4 * 4);
            int wv = *(const int*)(wo + k4 * 4);
            acc = __dp4a(hv, wv, acc);
        }
        out[(cta * NB_CTA + b) * O_DIM + o] = (float)acc * (1.0f / 1024.0f);
    }
}

// ---------------------------------------------------------------------------
// Launch
// ---------------------------------------------------------------------------
extern "C" void kernel_launch(void* const* d_in, const int* in_sizes, int n_in,
                              void* d_out, int out_size) {
    const float* inp = (const float*)d_in[0];   // [256,1024,64]
    const float* Wi  = (const float*)d_in[1];   // [256,64]
    const float* Wr  = (const float*)d_in[2];   // [256,256]
    const float* Wo  = (const float*)d_in[3];   // [16,256]
    const float* b   = (const float*)d_in[4];   // [256]
    float* out = (float*)d_out;                 // [256,16]

    const int total_w = H_DIM * K_TOT + O_DIM * H_DIM + H_DIM;
    prep_weights<<<(total_w + 255) / 256, 256>>>(Wi, Wr, Wo, b);
    prep_inputs<<<T_STEPS, 256>>>(inp);
    rnn_kernel<<<N_CTA, 256>>>(out);
}

// round 5
// speedup vs baseline: 3.2412x; 3.2412x over previous
#include <cuda_runtime.h>
#include <cstdint>

// Problem constants
#define T_STEPS 1024
#define B_TOT   256
#define I_DIM   64
#define H_DIM   256
#define O_DIM   16
#define K_TOT   320      // H_DIM + I_DIM (concatenated [h | x])
#define NB      2        // batches per CTA
#define N_CTA   128      // 128 * 2 = 256 batches, one CTA per SM
#define NTHR    512      // thread = (h_row 0..255, local batch 0..1)

// Scratch (device globals: no allocation allowed)
__device__ int8_t g_Wcat[H_DIM * K_TOT];          // [h_out][k]  int4 values in int8 (-8..7)
__device__ int8_t g_wo[O_DIM * H_DIM];            // [o][k]      int4 values in int8
__device__ float  g_b128[H_DIM];                  // 128 * b[n]
__device__ int8_t g_xT[(size_t)T_STEPS * B_TOT * I_DIM];  // transposed quantized inputs [t][b][i]

// ---------------------------------------------------------------------------
// Prep kernel 1: quantize weights & bias
// quantize(w, 4) -> clip(rint(w*8), -8, 7)  (value stored as the integer)
// ---------------------------------------------------------------------------
__global__ void prep_weights(const float* __restrict__ Wi,
                             const float* __restrict__ Wr,
                             const float* __restrict__ Wo,
                             const float* __restrict__ b) {
    int i = blockIdx.x * blockDim.x + threadIdx.x;
    const int NW = H_DIM * K_TOT;           // 81920
    const int NO = O_DIM * H_DIM;           // 4096
    if (i < NW) {
        int n = i / K_TOT, k = i % K_TOT;
        float v = (k < H_DIM) ? Wr[n * H_DIM + k] : Wi[n * I_DIM + (k - H_DIM)];
        int q = __float2int_rn(v * 8.0f);
        q = max(-8, min(7, q));
        g_Wcat[i] = (int8_t)q;
    } else if (i < NW + NO) {
        int j = i - NW;
        int q = __float2int_rn(Wo[j] * 8.0f);
        q = max(-8, min(7, q));
        g_wo[j] = (int8_t)q;
    } else if (i < NW + NO + H_DIM) {
        int n = i - (NW + NO);
        g_b128[n] = 128.0f * b[n];
    }
}

// ---------------------------------------------------------------------------
// Prep kernel 2: quantize inputs (8-bit) and transpose [B,T,I] -> [T,B,I]
// quantize(x, 8) -> clip(rint(x*128), -128, 127)
// ---------------------------------------------------------------------------
__global__ void prep_inputs(const float* __restrict__ inp) {
    int t = blockIdx.x;
    int tid = threadIdx.x;
    int i = tid & 63;
    int bq = tid >> 6;          // 0..3
    for (int it = 0; it < 64; it++) {
        int bb = it * 4 + bq;   // 0..255
        float v = inp[(size_t)bb * (T_STEPS * I_DIM) + (size_t)t * I_DIM + i];
        int q = __float2int_rn(v * 128.0f);
        q = max(-128, min(127, q));
        g_xT[(size_t)t * (B_TOT * I_DIM) + bb * I_DIM + i] = (int8_t)q;
    }
}

// ---------------------------------------------------------------------------
// Recurrent kernel: 128 CTAs (one per SM) x 2 batches, 512 threads.
// Thread (row, lb) computes h_next[row] for local batch lb via 80 dp4a over
// the broadcast [h|x] vector in smem. Double-buffered operand vector ->
// ONE __syncthreads per step. Exact integer arithmetic:
//   z = zi/1024 ; m*128 = relu(|zi|/8 + 128*b) ; h_int = rni(sign*m*128) clamp.
// ---------------------------------------------------------------------------
__global__ __launch_bounds__(NTHR, 1) void rnn_kernel(float* __restrict__ out) {
    // [buf][local_batch][k] : k<256 = h (int8 *128), 256..319 = x (int8 *128), pad to 384
    __shared__ __align__(16) int8_t hx[2][NB][384];

    const int tid = threadIdx.x;
    const int row = tid & 255;      // h_out index
    const int lb  = tid >> 8;       // local batch 0..1
    const int cta = blockIdx.x;

    // Weight row resident in registers (80 bytes = 20 uint4)
    uint4 w[20];
    {
        const uint4* wp = (const uint4*)(g_Wcat + row * K_TOT);
#pragma unroll
        for (int i = 0; i < 20; i++) w[i] = wp[i];
    }
    const float b128r = g_b128[row];

    // zero both buffers (h0 = 0, pad = 0)
    for (int i = tid; i < 2 * NB * 384 / 16; i += NTHR)
        ((uint4*)hx)[i] = make_uint4(0u, 0u, 0u, 0u);
    __syncthreads();

    // x_0 into buffer 0
    if (tid < 8) {
        int l = tid >> 2, c = tid & 3;
        uint4 xv = *(const uint4*)(g_xT + (size_t)(cta * NB + l) * I_DIM + c * 16);
        *(uint4*)(&hx[0][l][256 + c * 16]) = xv;
    }
    __syncthreads();

    int p = 0;
    for (int t = 0; t < T_STEPS; t++) {
        // issue x-prefetch for step t+1 (latency hidden under the dp4a loop)
        uint4 xv = make_uint4(0u, 0u, 0u, 0u);
        const bool do_x = (tid < 8) && (t + 1 < T_STEPS);
        if (do_x) {
            int l = tid >> 2, c = tid & 3;
            xv = *(const uint4*)(g_xT + (size_t)(t + 1) * (B_TOT * I_DIM)
                                 + (size_t)(cta * NB + l) * I_DIM + c * 16);
        }

        // 80 dp4a over broadcast smem vector, two accumulator chains
        const uint4* hp = (const uint4*)(&hx[p][lb][0]);
        int a0 = 0, a1 = 0;
#pragma unroll
        for (int kk = 0; kk < 20; kk += 2) {
            uint4 h0 = hp[kk];
            uint4 h1 = hp[kk + 1];
            a0 = __dp4a((int)h0.x, (int)w[kk].x, a0);
            a1 = __dp4a((int)h1.x, (int)w[kk + 1].x, a1);
            a0 = __dp4a((int)h0.y, (int)w[kk].y, a0);
            a1 = __dp4a((int)h1.y, (int)w[kk + 1].y, a1);
            a0 = __dp4a((int)h0.z, (int)w[kk].z, a0);
            a1 = __dp4a((int)h1.z, (int)w[kk + 1].z, a1);
            a0 = __dp4a((int)h0.w, (int)w[kk].w, a0);
            a1 = __dp4a((int)h1.w, (int)w[kk + 1].w, a1);
        }
        int zi = a0 + a1;

        // x for t+1 into the next buffer (arrived by now)
        if (do_x) {
            int l = tid >> 2, c = tid & 3;
            *(uint4*)(&hx[p ^ 1][l][256 + c * 16]) = xv;
        }

        // Epilogue: h_new = clip(rint(sign(z) * relu(|z|+b) * 128), -128, 127)
        float fz = (float)zi;                       // exact (|zi| < 2^20)
        float tt = fmaf(fabsf(fz), 0.125f, b128r);  // |zi|/8 + 128b  (single RN, matches ref)
        tt = fmaxf(tt, 0.0f);                       // relu
        float v = copysignf(tt, fz);                // sign(z)*m*128
        int r = __float2int_rn(v);                  // round half-even
        if (zi == 0) r = 0;                         // jnp.sign(0) == 0
        r = max(-128, min(127, r));
        hx[p ^ 1][lb][row] = (int8_t)r;

        p ^= 1;
        __syncthreads();                            // single barrier per step
    }

    // --- Output head: out[b][o] = (h_last . wo_q) / 1024  (exact in fp32) ---
    // h_last is in hx[p] (p == 0 after 1024 flips).
    if (tid < NB * O_DIM) {
        int bb = tid >> 4;   // local batch
        int o  = tid & 15;
        const uint4* hr = (const uint4*)(&hx[p][bb][0]);
        const uint4* wo = (const uint4*)(g_wo + o * H_DIM);
        int acc = 0;
#pragma unroll
        for (int k = 0; k < 16; k++) {
            uint4 hv = hr[k], wv = wo[k];
            acc = __dp4a((int)hv.x, (int)wv.x, acc);
            acc = __dp4a((int)hv.y, (int)wv.y, acc);
            acc = __dp4a((int)hv.z, (int)wv.z, acc);
            acc = __dp4a((int)hv.w, (int)wv.w, acc);
        }
        out[(cta * NB + bb) * O_DIM + o] = (float)acc * (1.0f / 1024.0f);
    }
}

// ---------------------------------------------------------------------------
// Launch
// ---------------------------------------------------------------------------
extern "C" void kernel_launch(void* const* d_in, const int* in_sizes, int n_in,
                              void* d_out, int out_size) {
    const float* inp = (const float*)d_in[0];   // [256,1024,64]
    const float* Wi  = (const float*)d_in[1];   // [256,64]
    const float* Wr  = (const float*)d_in[2];   // [256,256]
    const float* Wo  = (const float*)d_in[3];   // [16,256]
    const float* b   = (const float*)d_in[4];   // [256]
    float* out = (float*)d_out;                 // [256,16]

    const int total_w = H_DIM * K_TOT + O_DIM * H_DIM + H_DIM;
    prep_weights<<<(total_w + 255) / 256, 256>>>(Wi, Wr, Wo, b);
    prep_inputs<<<T_STEPS, 256>>>(inp);
    rnn_kernel<<<N_CTA, NTHR>>>(out);
}

// round 6
// speedup vs baseline: 3.3682x; 1.0392x over previous
#include <cuda_runtime.h>
#include <cstdint>

// Problem constants
#define T_STEPS 1024
#define B_TOT   256
#define I_DIM   64
#define H_DIM   256
#define O_DIM   16
#define K_TOT   320      // H_DIM + I_DIM
#define NB      2        // batches per CTA
#define N_CTA   128      // 128 * 2 = 256 batches, one CTA per SM
#define NTHR    512      // thread = (h_row 0..255, local batch 0..1)

#define X_SMEM_BYTES (T_STEPS * NB * I_DIM)   // 131072 = 128KB

// Scratch (device globals: no allocation allowed)
__device__ int8_t g_Wcat[H_DIM * K_TOT];   // [h_out][k] int4 values in int8 (-8..7)
__device__ int8_t g_wo[O_DIM * H_DIM];     // [o][k]     int4 values in int8
__device__ float  g_b128[H_DIM];           // 128 * b[n]

// ---------------------------------------------------------------------------
// Prep: quantize weights & bias.  quantize(w,4) -> clip(rint(w*8), -8, 7)
// ---------------------------------------------------------------------------
__global__ void prep_weights(const float* __restrict__ Wi,
                             const float* __restrict__ Wr,
                             const float* __restrict__ Wo,
                             const float* __restrict__ b) {
    int i = blockIdx.x * blockDim.x + threadIdx.x;
    const int NW = H_DIM * K_TOT;           // 81920
    const int NO = O_DIM * H_DIM;           // 4096
    if (i < NW) {
        int n = i / K_TOT, k = i % K_TOT;
        float v = (k < H_DIM) ? Wr[n * H_DIM + k] : Wi[n * I_DIM + (k - H_DIM)];
        int q = __float2int_rn(v * 8.0f);
        q = max(-8, min(7, q));
        g_Wcat[i] = (int8_t)q;
    } else if (i < NW + NO) {
        int j = i - NW;
        int q = __float2int_rn(Wo[j] * 8.0f);
        q = max(-8, min(7, q));
        g_wo[j] = (int8_t)q;
    } else if (i < NW + NO + H_DIM) {
        int n = i - (NW + NO);
        g_b128[n] = 128.0f * b[n];
    }
}

// ---------------------------------------------------------------------------
// One recurrence step for one (row, lb) thread.
//   hp:   read base of current h vector (16 uint4 = 256 B, broadcast in warp)
//   xp:   read base of x_t slice for this lb (4 uint4 = 64 B)
//   hdst: &hx[next_buf][lb][row]
// Exact integer arithmetic: z = zi/1024 ; m*128 = relu(|zi|/8 + 128*b);
// h_int = rni(sign(zi)*m*128) clamped to [-128,127].
// ---------------------------------------------------------------------------
__device__ __forceinline__ void step_one(const uint4* __restrict__ hp,
                                         const uint4* __restrict__ xp,
                                         const uint4 (&w)[20],
                                         float b128r,
                                         int8_t* hdst) {
    int a0 = 0, a1 = 0;
#pragma unroll
    for (int kk = 0; kk < 16; kk += 2) {
        uint4 h0 = hp[kk];
        uint4 h1 = hp[kk + 1];
        a0 = __dp4a((int)h0.x, (int)w[kk].x, a0);
        a1 = __dp4a((int)h1.x, (int)w[kk + 1].x, a1);
        a0 = __dp4a((int)h0.y, (int)w[kk].y, a0);
        a1 = __dp4a((int)h1.y, (int)w[kk + 1].y, a1);
        a0 = __dp4a((int)h0.z, (int)w[kk].z, a0);
        a1 = __dp4a((int)h1.z, (int)w[kk + 1].z, a1);
        a0 = __dp4a((int)h0.w, (int)w[kk].w, a0);
        a1 = __dp4a((int)h1.w, (int)w[kk + 1].w, a1);
    }
    {
        uint4 x0 = xp[0];
        uint4 x1 = xp[1];
        uint4 x2 = xp[2];
        uint4 x3 = xp[3];
        a0 = __dp4a((int)x0.x, (int)w[16].x, a0);
        a1 = __dp4a((int)x1.x, (int)w[17].x, a1);
        a0 = __dp4a((int)x0.y, (int)w[16].y, a0);
        a1 = __dp4a((int)x1.y, (int)w[17].y, a1);
        a0 = __dp4a((int)x0.z, (int)w[16].z, a0);
        a1 = __dp4a((int)x1.z, (int)w[17].z, a1);
        a0 = __dp4a((int)x0.w, (int)w[16].w, a0);
        a1 = __dp4a((int)x1.w, (int)w[17].w, a1);
        a0 = __dp4a((int)x2.x, (int)w[18].x, a0);
        a1 = __dp4a((int)x3.x, (int)w[19].x, a1);
        a0 = __dp4a((int)x2.y, (int)w[18].y, a0);
        a1 = __dp4a((int)x3.y, (int)w[19].y, a1);
        a0 = __dp4a((int)x2.z, (int)w[18].z, a0);
        a1 = __dp4a((int)x3.z, (int)w[19].z, a1);
        a0 = __dp4a((int)x2.w, (int)w[18].w, a0);
        a1 = __dp4a((int)x3.w, (int)w[19].w, a1);
    }
    int zi = a0 + a1;

    float fz = (float)zi;                        // exact (|zi| < 2^20)
    float tt = fmaf(fabsf(fz), 0.125f, b128r);   // |zi|/8 + 128b (single RN, matches ref)
    tt = fmaxf(tt, 0.0f);                        // relu
    float v = copysignf(tt, fz);                 // sign(z)*m*128
    int r = __float2int_rn(v);                   // round half-even
    if (zi == 0) r = 0;                          // jnp.sign(0) == 0
    r = max(-128, min(127, r));
    *hdst = (int8_t)r;
    __syncthreads();                             // single barrier per step
}

// ---------------------------------------------------------------------------
// Recurrent kernel: 128 CTAs (one per SM) x 2 batches, 512 threads.
// x quantized in-kernel into 128KB dynamic smem (each CTA preps only its own
// slice). T-loop unrolled x2 with explicit ping-pong h buffers so all smem
// bases are loop-invariant registers.
// ---------------------------------------------------------------------------
__global__ __launch_bounds__(NTHR, 1) void rnn_kernel(const float* __restrict__ inp,
                                                      float* __restrict__ out) {
    extern __shared__ __align__(16) int8_t xs[];        // [t][lb][64] int8, 128KB
    __shared__ __align__(16) int8_t hx[2][NB][256];     // ping-pong h (int8 *128)

    const int tid = threadIdx.x;
    const int row = tid & 255;      // h_out index
    const int lb  = tid >> 8;       // local batch 0..1
    const int cta = blockIdx.x;

    // Weight row resident in registers (80 bytes = 20 uint4)
    uint4 w[20];
    {
        const uint4* wp = (const uint4*)(g_Wcat + row * K_TOT);
#pragma unroll
        for (int i = 0; i < 20; i++) w[i] = wp[i];
    }
    const float b128r = g_b128[row];

    // --- Quantize this CTA's input slice into smem: [t][lb][i] ---
    // inp layout [B, T, I]; our batches are cta*NB .. cta*NB+NB-1 (contiguous).
    {
        const float4* ib = (const float4*)(inp + (size_t)(cta * NB) * (T_STEPS * I_DIM));
        const int NV = (NB * T_STEPS * I_DIM) / 4;     // 32768 float4 groups
#pragma unroll 4
        for (int v = tid; v < NV; v += NTHR) {
            float4 f4 = ib[v];
            int f = v * 4;                              // flat elem idx: lb*65536 + t*64 + i
            int l  = f >> 16;
            int t  = (f >> 6) & (T_STEPS - 1);
            int i0 = f & 63;
            int q0 = max(-128, min(127, __float2int_rn(f4.x * 128.0f)));
            int q1 = max(-128, min(127, __float2int_rn(f4.y * 128.0f)));
            int q2 = max(-128, min(127, __float2int_rn(f4.z * 128.0f)));
            int q3 = max(-128, min(127, __float2int_rn(f4.w * 128.0f)));
            unsigned pk = (q0 & 255) | ((q1 & 255) << 8) | ((q2 & 255) << 16) | ((q3 & 255) << 24);
            *(unsigned*)(xs + t * (NB * I_DIM) + l * I_DIM + i0) = pk;
        }
    }
    // zero both h buffers (h0 = 0): 1KB total = 64 uint4
    if (tid < 64) ((uint4*)hx)[tid] = make_uint4(0u, 0u, 0u, 0u);
    __syncthreads();

    // Loop-invariant bases
    const uint4* hb0 = (const uint4*)(&hx[0][lb][0]);
    const uint4* hb1 = (const uint4*)(&hx[1][lb][0]);
    int8_t* hd0 = &hx[0][lb][row];
    int8_t* hd1 = &hx[1][lb][row];
    const uint4* xp = (const uint4*)(xs + lb * I_DIM);   // advances 8 uint4 (128B) per step

    for (int t = 0; t < T_STEPS; t += 2) {
        step_one(hb0, xp, w, b128r, hd1);   // reads hx0, writes hx1
        xp += 8;
        step_one(hb1, xp, w, b128r, hd0);   // reads hx1, writes hx0
        xp += 8;
    }
    // final h is in hx[0]

    // --- Output head: out[b][o] = (h_last . wo_q) / 1024  (exact in fp32) ---
    if (tid < NB * O_DIM) {
        int bb = tid >> 4;   // local batch
        int o  = tid & 15;
        const uint4* hr = (const uint4*)(&hx[0][bb][0]);
        const uint4* wo = (const uint4*)(g_wo + o * H_DIM);
        int acc = 0;
#pragma unroll
        for (int k = 0; k < 16; k++) {
            uint4 hv = hr[k], wv = wo[k];
            acc = __dp4a((int)hv.x, (int)wv.x, acc);
            acc = __dp4a((int)hv.y, (int)wv.y, acc);
            acc = __dp4a((int)hv.z, (int)wv.z, acc);
            acc = __dp4a((int)hv.w, (int)wv.w, acc);
        }
        out[(cta * NB + bb) * O_DIM + o] = (float)acc * (1.0f / 1024.0f);
    }
}

// ---------------------------------------------------------------------------
// Launch
// ---------------------------------------------------------------------------
extern "C" void kernel_launch(void* const* d_in, const int* in_sizes, int n_in,
                              void* d_out, int out_size) {
    const float* inp = (const float*)d_in[0];   // [256,1024,64]
    const float* Wi  = (const float*)d_in[1];   // [256,64]
    const float* Wr  = (const float*)d_in[2];   // [256,256]
    const float* Wo  = (const float*)d_in[3];   // [16,256]
    const float* b   = (const float*)d_in[4];   // [256]
    float* out = (float*)d_out;                 // [256,16]

    // Host-side attribute set (idempotent, not a stream op, not an allocation).
    cudaFuncSetAttribute(rnn_kernel, cudaFuncAttributeMaxDynamicSharedMemorySize,
                         X_SMEM_BYTES);

    const int total_w = H_DIM * K_TOT + O_DIM * H_DIM + H_DIM;
    prep_weights<<<(total_w + 255) / 256, 256>>>(Wi, Wr, Wo, b);
    rnn_kernel<<<N_CTA, NTHR, X_SMEM_BYTES>>>(inp, out);
}